// round 1
// baseline (speedup 1.0000x reference)
#include <cuda_runtime.h>

#define J 5

struct Params {
    float wl[J], bl[J], wt[J], bt[J], we[J], r1[J], c1[J];
    float W2[J*J], b2[J], Wo[J], bo;
};

__device__ Params d_P;

__global__ void setup_kernel(const float* __restrict__ wlogm, const float* __restrict__ blogm,
                             const float* __restrict__ wttm,  const float* __restrict__ bttm,
                             const float* __restrict__ wexp,  const float* __restrict__ bexp,
                             const float* __restrict__ W1,    const float* __restrict__ b1,
                             const float* __restrict__ W2,    const float* __restrict__ b2,
                             const float* __restrict__ Wo,    const float* __restrict__ bo)
{
    if (threadIdx.x == 0 && blockIdx.x == 0) {
        for (int j = 0; j < J; ++j) {
            d_P.wl[j] = expf(wlogm[j]);
            d_P.bl[j] = blogm[j];
            d_P.wt[j] = expf(wttm[j]);
            d_P.bt[j] = bttm[j];
            d_P.we[j] = expf(wexp[j]);
            float r = 0.f, c = b1[j];
            for (int k = 0; k < J; ++k) {
                float w = W1[j*J + k];
                r += w;
                c += w * bexp[k];
            }
            d_P.r1[j] = r;
            d_P.c1[j] = c;
            d_P.b2[j] = b2[j];
            d_P.Wo[j] = Wo[j];
            for (int k = 0; k < J; ++k) d_P.W2[j*J + k] = W2[j*J + k];
        }
        d_P.bo = bo[0];
    }
}

// tanh via exp: accurate to ~2 ulp of ex2.approx, stable at |x| -> inf.
__device__ __forceinline__ float fast_tanh(float x) {
    float e = __expf(2.f * fabsf(x));             // ex2.approx
    float t = 1.f - __fdividef(2.f, e + 1.f);     // rcp.approx; e=inf -> t=1
    return x >= 0.f ? t : -t;
}

__device__ __forceinline__ float fast_sigmoid(float x) {
    return __fdividef(1.f, 1.f + __expf(-x));     // x<<0: exp=inf -> 0; x>>0 -> 1
}

// Stable softplus + sigmoid from one exp: e = exp(-|z|) in (0,1].
__device__ __forceinline__ void softplus_sig(float z, float& sp, float& sg) {
    float e   = __expf(-fabsf(z));
    float inv = __fdividef(1.f, 1.f + e);
    sg = (z >= 0.f) ? inv : 1.f - inv;
    sp = fmaxf(z, 0.f) + __logf(1.f + e);
}

__global__ __launch_bounds__(256)
void smile_kernel(const float* __restrict__ ttm,
                  const float* __restrict__ logm,
                  float* __restrict__ out, int B)
{
    __shared__ Params P;
    {
        const float* src = reinterpret_cast<const float*>(&d_P);
        float* dst = reinterpret_cast<float*>(&P);
        for (int i = threadIdx.x; i < (int)(sizeof(Params)/4); i += blockDim.x)
            dst[i] = src[i];
    }
    __syncthreads();

    int i = blockIdx.x * blockDim.x + threadIdx.x;
    if (i >= B) return;

    float l = logm[i];
    float t = ttm[i];

    // s and its derivatives wrt ttm (st) and logm (sl, sll)
    float s = 0.f, st = 0.f, sl = 0.f, sll = 0.f;
    #pragma unroll
    for (int j = 0; j < J; ++j) {
        float a  = fmaf(l, P.wl[j], P.bl[j]);
        float t1 = fast_tanh(a + 0.5f);
        float t2 = fast_tanh(0.5f * a);
        float u1 = fmaf(-t1, t1, 1.f);
        float u2 = fmaf(-t2, t2, 1.f);
        float g   = fmaf(a, t1, 5e-4f) - t2;
        float gp  = t1 + a * u1 - 0.5f * u2;
        float gpp = 2.f * u1 * fmaf(-a, t1, 1.f) + 0.5f * t2 * u2;
        float rq;
        asm("rsqrt.approx.f32 %0, %1;" : "=f"(rq) : "f"(g));
        float T   = g * rq;                       // sqrt(g)
        float Tp  = 0.5f * gp * rq;
        float Tpp = (0.5f * gpp - 0.25f * gp * gp * rq * rq) * rq;

        float b   = fmaf(t, P.wt[j], P.bt[j]);
        float sg  = fast_sigmoid(b);
        float sgp = sg * (1.f - sg);

        float w   = P.we[j];
        s   = fmaf(w, T * sg, s);
        st  = fmaf(w * P.wt[j], T * sgp, st);
        float wsg = w * sg * P.wl[j];
        sl  = fmaf(wsg, Tp, sl);
        sll = fmaf(wsg * P.wl[j], Tpp, sll);
    }

    // Layer 1 collapses to scalar input: z1_j = s * r1_j + c1_j
    float h1[J], d1[J], dd1[J];
    #pragma unroll
    for (int j = 0; j < J; ++j) {
        float z = fmaf(s, P.r1[j], P.c1[j]);
        float sp, sg;
        softplus_sig(z, sp, sg);
        h1[j]  = sp;
        d1[j]  = sg * P.r1[j];                         // dh1/ds
        dd1[j] = sg * (1.f - sg) * P.r1[j] * P.r1[j];  // d2h1/ds2
    }

    // Layer 2 + output head, with F'(s), F''(s)
    float o = P.bo, F1 = 0.f, F2 = 0.f;
    #pragma unroll
    for (int j = 0; j < J; ++j) {
        float z2 = P.b2[j], q = 0.f, m = 0.f;
        #pragma unroll
        for (int k = 0; k < J; ++k) {
            float w = P.W2[j*J + k];
            z2 = fmaf(w, h1[k],  z2);
            q  = fmaf(w, d1[k],  q);
            m  = fmaf(w, dd1[k], m);
        }
        float sp2, sg2;
        softplus_sig(z2, sp2, sg2);
        o  = fmaf(P.Wo[j], sp2, o);
        F1 = fmaf(P.Wo[j], sg2 * q, F1);
        F2 = fmaf(P.Wo[j], fmaf(sg2 * (1.f - sg2), q * q, sg2 * m), F2);
    }

    out[i]         = o;                        // output
    out[B + i]     = F1 * st;                  // grad_ttm1
    out[2*B + i]   = F1 * sl;                  // grad_logm1
    out[3*B + i]   = fmaf(F2, sl * sl, F1 * sll);  // grad_logm2
}

extern "C" void kernel_launch(void* const* d_in, const int* in_sizes, int n_in,
                              void* d_out, int out_size)
{
    const float* ttm  = (const float*)d_in[0];
    const float* logm = (const float*)d_in[1];

    setup_kernel<<<1, 32>>>((const float*)d_in[2],  (const float*)d_in[3],
                            (const float*)d_in[4],  (const float*)d_in[5],
                            (const float*)d_in[6],  (const float*)d_in[7],
                            (const float*)d_in[8],  (const float*)d_in[9],
                            (const float*)d_in[10], (const float*)d_in[11],
                            (const float*)d_in[12], (const float*)d_in[13]);

    int B = in_sizes[0];
    int blocks = (B + 255) / 256;
    smile_kernel<<<blocks, 256>>>(ttm, logm, (float*)d_out, B);
}

// round 2
// speedup vs baseline: 1.0435x; 1.0435x over previous
#include <cuda_runtime.h>

#define J 5
#define NS 4
#define L2E 1.4426950408889634f
#define LN2 0.6931471805599453f
#define E1F 2.7182818284590452f

// Packed runtime-constant table, filled by setup_kernel each launch.
// [0..4]   per-j: {wl*L2E, bl*L2E, -wt*L2E, -bt*L2E}
// [5..9]   per-j: {we, we*wt, we*wl, we*wl*wl}
// [10..14] per-j: {r1*L2E, c1*L2E, r1, (j==0 ? bo : 0)}
// [15..19] per-j: {W2[j][0..3]}
// [20..24] per-j: {W2[j][4], b2[j], Wo[j], Wo[j]*LN2}
__device__ float4 d_c[25];

__device__ __forceinline__ float ex2f(float x){ float r; asm("ex2.approx.f32 %0,%1;":"=f"(r):"f"(x)); return r; }
__device__ __forceinline__ float lg2f_(float x){ float r; asm("lg2.approx.f32 %0,%1;":"=f"(r):"f"(x)); return r; }
__device__ __forceinline__ float rcpf(float x){ float r; asm("rcp.approx.f32 %0,%1;":"=f"(r):"f"(x)); return r; }
__device__ __forceinline__ float rsqf(float x){ float r; asm("rsqrt.approx.f32 %0,%1;":"=f"(r):"f"(x)); return r; }

__global__ void setup_kernel(const float* __restrict__ wlogm, const float* __restrict__ blogm,
                             const float* __restrict__ wttm,  const float* __restrict__ bttm,
                             const float* __restrict__ wexp,  const float* __restrict__ bexp,
                             const float* __restrict__ W1,    const float* __restrict__ b1,
                             const float* __restrict__ W2,    const float* __restrict__ b2,
                             const float* __restrict__ Wo,    const float* __restrict__ bo)
{
    if (threadIdx.x == 0 && blockIdx.x == 0) {
        for (int j = 0; j < J; ++j) {
            float wl = expf(wlogm[j]);
            float wt = expf(wttm[j]);
            float we = expf(wexp[j]);
            d_c[j]     = make_float4(wl * L2E, blogm[j] * L2E, -wt * L2E, -bttm[j] * L2E);
            d_c[5+j]   = make_float4(we, we * wt, we * wl, we * wl * wl);
            float r = 0.f, c = b1[j];
            for (int k = 0; k < J; ++k) {
                float w = W1[j*J + k];
                r += w;
                c += w * bexp[k];
            }
            d_c[10+j]  = make_float4(r * L2E, c * L2E, r, j == 0 ? bo[0] : 0.f);
            d_c[15+j]  = make_float4(W2[j*J+0], W2[j*J+1], W2[j*J+2], W2[j*J+3]);
            d_c[20+j]  = make_float4(W2[j*J+4], b2[j], Wo[j], Wo[j] * LN2);
        }
    }
}

__global__ __launch_bounds__(256)
void smile_kernel(const float4* __restrict__ ttm4,
                  const float4* __restrict__ logm4,
                  float* __restrict__ out, int B)
{
    __shared__ float4 sc[25];
    if (threadIdx.x < 25) sc[threadIdx.x] = d_c[threadIdx.x];
    __syncthreads();

    int v = blockIdx.x * blockDim.x + threadIdx.x;
    int nvec = B >> 2;
    if (v >= nvec) return;

    float4 t4 = ttm4[v];
    float4 l4 = logm4[v];
    float tt[NS] = {t4.x, t4.y, t4.z, t4.w};
    float ll[NS] = {l4.x, l4.y, l4.z, l4.w};

    float s[NS]   = {0.f,0.f,0.f,0.f};
    float st[NS]  = {0.f,0.f,0.f,0.f};
    float sl[NS]  = {0.f,0.f,0.f,0.f};
    float sll[NS] = {0.f,0.f,0.f,0.f};

    // ---- Part 1: smile term, sigmoid term, and derivatives of s(t,l) ----
    #pragma unroll
    for (int j = 0; j < J; ++j) {
        float4 pa = sc[j];      // wl*L2E, bl*L2E, -wt*L2E, -bt*L2E
        float4 pb = sc[5+j];    // we, we*wt, we*wl, we*wl^2
        #pragma unroll
        for (int n = 0; n < NS; ++n) {
            float a2 = fmaf(ll[n], pa.x, pa.y);       // a * log2(e)
            float a  = a2 * LN2;                      // a
            float E  = ex2f(a2);                      // e^a
            float E2 = E * E;                         // e^{2a}
            float t1 = fmaf(-2.f, rcpf(fmaf(E2, E1F, 1.f)), 1.f);  // tanh(a+0.5)
            float t2 = fmaf(-2.f, rcpf(E + 1.f), 1.f);             // tanh(a/2)
            float u1 = fmaf(-t1, t1, 1.f);
            float u2 = fmaf(-t2, t2, 1.f);
            float hu2 = 0.5f * u2;
            float g   = fmaf(a, t1, 5e-4f) - t2;
            float gp  = fmaf(a, u1, t1) - hu2;
            float mm  = u1 * fmaf(-a, t1, 1.f);
            float gpp = fmaf(t2, hu2, mm + mm);
            float rq  = rsqf(g);
            float T   = g * rq;                       // sqrt(g)
            float hgp = 0.5f * gp;
            float Tp  = hgp * rq;
            float rr  = rq * rq;
            float Tpp = fmaf(-(hgp * hgp), rr, 0.5f * gpp) * rq;

            float eb  = ex2f(fmaf(tt[n], pa.z, pa.w));  // e^{-b}
            float sg  = rcpf(1.f + eb);                 // sigmoid(b)
            float sgp = sg * sg * eb;                   // sigmoid'

            s[n]   = fmaf(pb.x, T * sg,    s[n]);
            st[n]  = fmaf(pb.y, T * sgp,   st[n]);
            sl[n]  = fmaf(pb.z, sg * Tp,   sl[n]);
            sll[n] = fmaf(pb.w, sg * Tpp,  sll[n]);
        }
    }

    // ---- Layer 1 (collapses to scalar s): h1, dh1/ds, d2h1/ds2 ----
    float h1[NS][J], d1[NS][J], dd1[NS][J];
    #pragma unroll
    for (int j = 0; j < J; ++j) {
        float4 pl = sc[10+j];   // r1*L2E, c1*L2E, r1, (bo)
        #pragma unroll
        for (int n = 0; n < NS; ++n) {
            float E  = ex2f(fmaf(s[n], pl.x, pl.y));  // e^{z1}
            float p  = 1.f + E;
            float r  = rcpf(p);                       // 1 - sigmoid
            float sg = 1.f - r;                       // sigmoid(z1)
            h1[n][j]  = lg2f_(p) * LN2;               // softplus(z1)
            float d   = sg * pl.z;
            d1[n][j]  = d;
            dd1[n][j] = d * (r * pl.z);
        }
    }

    // ---- Layer 2 + head: o(s), F'(s), F''(s) ----
    float bo = sc[10].w;
    float o[NS]  = {bo, bo, bo, bo};
    float F1[NS] = {0.f,0.f,0.f,0.f};
    float F2[NS] = {0.f,0.f,0.f,0.f};
    #pragma unroll
    for (int j = 0; j < J; ++j) {
        float4 wa = sc[15+j];   // W2 row [0..3]
        float4 wb = sc[20+j];   // W2[4], b2, Wo, Wo*LN2
        #pragma unroll
        for (int n = 0; n < NS; ++n) {
            float z2 = wb.y, q = 0.f, m = 0.f;
            z2 = fmaf(wa.x, h1[n][0], z2); q = fmaf(wa.x, d1[n][0], q); m = fmaf(wa.x, dd1[n][0], m);
            z2 = fmaf(wa.y, h1[n][1], z2); q = fmaf(wa.y, d1[n][1], q); m = fmaf(wa.y, dd1[n][1], m);
            z2 = fmaf(wa.z, h1[n][2], z2); q = fmaf(wa.z, d1[n][2], q); m = fmaf(wa.z, dd1[n][2], m);
            z2 = fmaf(wa.w, h1[n][3], z2); q = fmaf(wa.w, d1[n][3], q); m = fmaf(wa.w, dd1[n][3], m);
            z2 = fmaf(wb.x, h1[n][4], z2); q = fmaf(wb.x, d1[n][4], q); m = fmaf(wb.x, dd1[n][4], m);

            float E   = ex2f(z2 * L2E);
            float p   = 1.f + E;
            float r   = rcpf(p);
            float sg2 = 1.f - r;
            o[n]  = fmaf(wb.w, lg2f_(p), o[n]);              // Wo*softplus(z2) (ln2 folded)
            F1[n] = fmaf(wb.z, sg2 * q, F1[n]);
            float inner = fmaf(sg2, m, (sg2 * r) * (q * q)); // sg2'(q^2) + sg2*m
            F2[n] = fmaf(wb.z, inner, F2[n]);
        }
    }

    // ---- Epilogue: chain rule to (out, d/dttm, d/dlogm, d2/dlogm2) ----
    float4 r0, r1v, r2v, r3v;
    float* p0 = &r0.x; float* p1 = &r1v.x; float* p2 = &r2v.x; float* p3 = &r3v.x;
    #pragma unroll
    for (int n = 0; n < NS; ++n) {
        p0[n] = o[n];
        p1[n] = F1[n] * st[n];
        p2[n] = F1[n] * sl[n];
        p3[n] = fmaf(F2[n], sl[n] * sl[n], F1[n] * sll[n]);
    }
    reinterpret_cast<float4*>(out)[v]                  = r0;
    reinterpret_cast<float4*>(out + B)[v]              = r1v;
    reinterpret_cast<float4*>(out + 2*(size_t)B)[v]    = r2v;
    reinterpret_cast<float4*>(out + 3*(size_t)B)[v]    = r3v;
}

extern "C" void kernel_launch(void* const* d_in, const int* in_sizes, int n_in,
                              void* d_out, int out_size)
{
    const float* ttm  = (const float*)d_in[0];
    const float* logm = (const float*)d_in[1];

    setup_kernel<<<1, 32>>>((const float*)d_in[2],  (const float*)d_in[3],
                            (const float*)d_in[4],  (const float*)d_in[5],
                            (const float*)d_in[6],  (const float*)d_in[7],
                            (const float*)d_in[8],  (const float*)d_in[9],
                            (const float*)d_in[10], (const float*)d_in[11],
                            (const float*)d_in[12], (const float*)d_in[13]);

    int B = in_sizes[0];
    int nvec = B >> 2;                       // B = 2^21, divisible by 4
    int blocks = (nvec + 255) / 256;
    smile_kernel<<<blocks, 256>>>((const float4*)ttm, (const float4*)logm,
                                  (float*)d_out, B);
}

// round 3
// speedup vs baseline: 1.4160x; 1.3569x over previous
#include <cuda_runtime.h>

#define J 5
#define NS 4
#define L2E 1.4426950408889634f
#define LN2 0.6931471805599453f
#define E1F 2.7182818284590452f

#define TABN 2048
#define TABH 0.0078125f      // 1/128
#define TABIH 128.0f

// part-1 constants: [0..4] {wl*L2E, bl*L2E, -wt*L2E, -bt*L2E}
//                   [5..9] {we, we*wt, we*wl, we*wl*wl}
__device__ float4 d_c[10];
// F(s) table: {F, F', F'', F'''} at s = i/128
__device__ float4 d_tab[TABN];

__device__ __forceinline__ float ex2f(float x){ float r; asm("ex2.approx.f32 %0,%1;":"=f"(r):"f"(x)); return r; }
__device__ __forceinline__ float rcpf(float x){ float r; asm("rcp.approx.f32 %0,%1;":"=f"(r):"f"(x)); return r; }
__device__ __forceinline__ float rsqf(float x){ float r; asm("rsqrt.approx.f32 %0,%1;":"=f"(r):"f"(x)); return r; }

__global__ void setup_kernel(const float* __restrict__ wlogm, const float* __restrict__ blogm,
                             const float* __restrict__ wttm,  const float* __restrict__ bttm,
                             const float* __restrict__ wexp)
{
    if (threadIdx.x == 0 && blockIdx.x == 0) {
        for (int j = 0; j < J; ++j) {
            float wl = expf(wlogm[j]);
            float wt = expf(wttm[j]);
            float we = expf(wexp[j]);
            d_c[j]   = make_float4(wl * L2E, blogm[j] * L2E, -wt * L2E, -bttm[j] * L2E);
            d_c[5+j] = make_float4(we, we * wt, we * wl, we * wl * wl);
        }
    }
}

// Build table of F(s) = Wo.softplus(W2.softplus(r1*s + c1) + b2) + bo and
// its first three derivatives wrt the scalar s. 2048 threads, one node each.
__global__ void table_kernel(const float* __restrict__ bexp,
                             const float* __restrict__ W1, const float* __restrict__ b1,
                             const float* __restrict__ W2, const float* __restrict__ b2,
                             const float* __restrict__ Wo, const float* __restrict__ bo)
{
    int i = blockIdx.x * blockDim.x + threadIdx.x;
    if (i >= TABN) return;
    float s = (float)i * TABH;

    float h1[J], d1[J], dd1[J], ddd1[J];
    for (int j = 0; j < J; ++j) {
        float r = 0.f, c = b1[j];
        for (int k = 0; k < J; ++k) {
            float w = W1[j*J + k];
            r += w;
            c += w * bexp[k];
        }
        float z  = r * s + c;
        float az = fabsf(z);
        float e  = expf(-az);
        float inv = 1.f / (1.f + e);
        float sg  = (z >= 0.f) ? inv : 1.f - inv;   // sigmoid(z)
        float sg1 = sg * (1.f - sg);
        float sg2 = sg1 * (1.f - 2.f * sg);
        h1[j]   = fmaxf(z, 0.f) + log1pf(e);        // softplus(z)
        d1[j]   = sg * r;
        dd1[j]  = sg1 * r * r;
        ddd1[j] = sg2 * r * r * r;
    }

    float F = bo[0], F1 = 0.f, F2 = 0.f, F3 = 0.f;
    for (int j = 0; j < J; ++j) {
        float z2 = b2[j], q = 0.f, m = 0.f, n3 = 0.f;
        for (int k = 0; k < J; ++k) {
            float w = W2[j*J + k];
            z2 += w * h1[k];
            q  += w * d1[k];
            m  += w * dd1[k];
            n3 += w * ddd1[k];
        }
        float az = fabsf(z2);
        float e  = expf(-az);
        float inv = 1.f / (1.f + e);
        float sg  = (z2 >= 0.f) ? inv : 1.f - inv;
        float sp  = fmaxf(z2, 0.f) + log1pf(e);
        float sg1 = sg * (1.f - sg);
        float sg2 = sg1 * (1.f - 2.f * sg);
        float wo = Wo[j];
        F  += wo * sp;
        F1 += wo * sg * q;
        F2 += wo * (sg1 * q * q + sg * m);
        F3 += wo * (sg2 * q * q * q + 3.f * sg1 * q * m + sg * n3);
    }
    d_tab[i] = make_float4(F, F1, F2, F3);
}

__global__ __launch_bounds__(256)
void smile_kernel(const float4* __restrict__ ttm4,
                  const float4* __restrict__ logm4,
                  float* __restrict__ out, int B)
{
    __shared__ float4 sc[10];
    if (threadIdx.x < 10) sc[threadIdx.x] = d_c[threadIdx.x];
    __syncthreads();

    int v = blockIdx.x * blockDim.x + threadIdx.x;
    int nvec = B >> 2;
    if (v >= nvec) return;

    float4 t4 = ttm4[v];
    float4 l4 = logm4[v];
    float tt[NS] = {t4.x, t4.y, t4.z, t4.w};
    float ll[NS] = {l4.x, l4.y, l4.z, l4.w};

    float s[NS]   = {0.f,0.f,0.f,0.f};
    float st[NS]  = {0.f,0.f,0.f,0.f};
    float sl[NS]  = {0.f,0.f,0.f,0.f};
    float sll[NS] = {0.f,0.f,0.f,0.f};

    // ---- Part 1: smile term, sigmoid term, derivatives of s(t,l) ----
    #pragma unroll
    for (int j = 0; j < J; ++j) {
        float4 pa = sc[j];      // wl*L2E, bl*L2E, -wt*L2E, -bt*L2E
        float4 pb = sc[5+j];    // we, we*wt, we*wl, we*wl^2
        #pragma unroll
        for (int n = 0; n < NS; ++n) {
            float a2 = fmaf(ll[n], pa.x, pa.y);       // a * log2(e)
            float a  = a2 * LN2;
            float E  = ex2f(a2);                      // e^a
            float E2 = E * E;
            float t1 = fmaf(-2.f, rcpf(fmaf(E2, E1F, 1.f)), 1.f);  // tanh(a+0.5)
            float t2 = fmaf(-2.f, rcpf(E + 1.f), 1.f);             // tanh(a/2)
            float u1 = fmaf(-t1, t1, 1.f);
            float u2 = fmaf(-t2, t2, 1.f);
            float hu2 = 0.5f * u2;
            float g   = fmaf(a, t1, 5e-4f) - t2;
            float gp  = fmaf(a, u1, t1) - hu2;
            float mm  = u1 * fmaf(-a, t1, 1.f);
            float gpp = fmaf(t2, hu2, mm + mm);
            float rq  = rsqf(g);
            float T   = g * rq;                       // sqrt(g)
            float hgp = 0.5f * gp;
            float Tp  = hgp * rq;
            float rr  = rq * rq;
            float Tpp = fmaf(-(hgp * hgp), rr, 0.5f * gpp) * rq;

            float eb  = ex2f(fmaf(tt[n], pa.z, pa.w));  // e^{-b}
            float sg  = rcpf(1.f + eb);                 // sigmoid(b)
            float sgp = sg * sg * eb;                   // sigmoid'

            s[n]   = fmaf(pb.x, T * sg,   s[n]);
            st[n]  = fmaf(pb.y, T * sgp,  st[n]);
            sl[n]  = fmaf(pb.z, sg * Tp,  sl[n]);
            sll[n] = fmaf(pb.w, sg * Tpp, sll[n]);
        }
    }

    // ---- Layers via table: nearest-node Taylor of F, F', F'' ----
    float4 r0, r1v, r2v, r3v;
    float* p0 = &r0.x; float* p1 = &r1v.x; float* p2 = &r2v.x; float* p3 = &r3v.x;
    #pragma unroll
    for (int n = 0; n < NS; ++n) {
        int i = __float2int_rn(s[n] * TABIH);
        i = min(i, TABN - 1);                       // s >= 0 always
        float d = fmaf((float)i, -TABH, s[n]);
        float4 c = __ldg(&d_tab[i]);
        float F2v = fmaf(c.w, d, c.z);
        float F1v = fmaf(fmaf(0.5f * c.w, d, c.z), d, c.y);
        float Fv  = fmaf(fmaf(fmaf(0.16666667f * c.w, d, 0.5f * c.z), d, c.y), d, c.x);

        p0[n] = Fv;
        p1[n] = F1v * st[n];
        p2[n] = F1v * sl[n];
        p3[n] = fmaf(F2v, sl[n] * sl[n], F1v * sll[n]);
    }
    reinterpret_cast<float4*>(out)[v]               = r0;
    reinterpret_cast<float4*>(out + B)[v]           = r1v;
    reinterpret_cast<float4*>(out + 2*(size_t)B)[v] = r2v;
    reinterpret_cast<float4*>(out + 3*(size_t)B)[v] = r3v;
}

extern "C" void kernel_launch(void* const* d_in, const int* in_sizes, int n_in,
                              void* d_out, int out_size)
{
    const float* ttm  = (const float*)d_in[0];
    const float* logm = (const float*)d_in[1];

    setup_kernel<<<1, 32>>>((const float*)d_in[2], (const float*)d_in[3],
                            (const float*)d_in[4], (const float*)d_in[5],
                            (const float*)d_in[6]);

    table_kernel<<<TABN/256, 256>>>((const float*)d_in[7],
                                    (const float*)d_in[8],  (const float*)d_in[9],
                                    (const float*)d_in[10], (const float*)d_in[11],
                                    (const float*)d_in[12], (const float*)d_in[13]);

    int B = in_sizes[0];
    int nvec = B >> 2;
    int blocks = (nvec + 255) / 256;
    smile_kernel<<<blocks, 256>>>((const float4*)ttm, (const float4*)logm,
                                  (float*)d_out, B);
}

// round 4
// speedup vs baseline: 1.4890x; 1.0516x over previous
#include <cuda_runtime.h>

#define J 5
#define NS 4
#define L2E 1.4426950408889634f
#define LN2 0.6931471805599453f
#define E1F 2.7182818284590452f

#define TABN 2048
#define TABH 0.0078125f      // 1/128
#define TABIH 128.0f

// F(s) table: {F, F', F'', F'''} at s = i/128
__device__ float4 d_tab[TABN];

__device__ __forceinline__ float ex2f(float x){ float r; asm("ex2.approx.f32 %0,%1;":"=f"(r):"f"(x)); return r; }
__device__ __forceinline__ float rcpf(float x){ float r; asm("rcp.approx.f32 %0,%1;":"=f"(r):"f"(x)); return r; }
__device__ __forceinline__ float rsqf(float x){ float r; asm("rsqrt.approx.f32 %0,%1;":"=f"(r):"f"(x)); return r; }

// Build table of F(s) = Wo.softplus(W2.softplus(r1*s + c1) + b2) + bo and
// its first three derivatives wrt the scalar s. One node per thread.
__global__ void table_kernel(const float* __restrict__ bexp,
                             const float* __restrict__ W1, const float* __restrict__ b1,
                             const float* __restrict__ W2, const float* __restrict__ b2,
                             const float* __restrict__ Wo, const float* __restrict__ bo)
{
    int i = blockIdx.x * blockDim.x + threadIdx.x;
    if (i >= TABN) return;
    float s = (float)i * TABH;

    float h1[J], d1[J], dd1[J], ddd1[J];
    for (int j = 0; j < J; ++j) {
        float r = 0.f, c = b1[j];
        for (int k = 0; k < J; ++k) {
            float w = W1[j*J + k];
            r += w;
            c += w * bexp[k];
        }
        float z  = r * s + c;
        float az = fabsf(z);
        float e  = expf(-az);
        float inv = 1.f / (1.f + e);
        float sg  = (z >= 0.f) ? inv : 1.f - inv;   // sigmoid(z)
        float sg1 = sg * (1.f - sg);
        float sg2 = sg1 * (1.f - 2.f * sg);
        h1[j]   = fmaxf(z, 0.f) + log1pf(e);        // softplus(z)
        d1[j]   = sg * r;
        dd1[j]  = sg1 * r * r;
        ddd1[j] = sg2 * r * r * r;
    }

    float F = bo[0], F1 = 0.f, F2 = 0.f, F3 = 0.f;
    for (int j = 0; j < J; ++j) {
        float z2 = b2[j], q = 0.f, m = 0.f, n3 = 0.f;
        for (int k = 0; k < J; ++k) {
            float w = W2[j*J + k];
            z2 += w * h1[k];
            q  += w * d1[k];
            m  += w * dd1[k];
            n3 += w * ddd1[k];
        }
        float az = fabsf(z2);
        float e  = expf(-az);
        float inv = 1.f / (1.f + e);
        float sg  = (z2 >= 0.f) ? inv : 1.f - inv;
        float sp  = fmaxf(z2, 0.f) + log1pf(e);
        float sg1 = sg * (1.f - sg);
        float sg2 = sg1 * (1.f - 2.f * sg);
        float wo = Wo[j];
        F  += wo * sp;
        F1 += wo * sg * q;
        F2 += wo * (sg1 * q * q + sg * m);
        F3 += wo * (sg2 * q * q * q + 3.f * sg1 * q * m + sg * n3);
    }
    d_tab[i] = make_float4(F, F1, F2, F3);
}

__global__ __launch_bounds__(256)
void smile_kernel(const float4* __restrict__ ttm4,
                  const float4* __restrict__ logm4,
                  float4* __restrict__ o0, float4* __restrict__ o1,
                  float4* __restrict__ o2, float4* __restrict__ o3,
                  const float* __restrict__ wlogm, const float* __restrict__ blogm,
                  const float* __restrict__ wttm,  const float* __restrict__ bttm,
                  const float* __restrict__ wexp,
                  int nvec)
{
    // Each block builds its own constant table (5 threads, 3 expf each —
    // ~200 cyc amortized over 1024 samples). No setup kernel needed.
    // sc[0..4]: {wl*L2E, bl*L2E, -wt*L2E, -bt*L2E}
    // sc[5..9]: {we, we*wt, we*wl, we*wl*wl}
    __shared__ float4 sc[10];
    if (threadIdx.x < J) {
        int j = threadIdx.x;
        float wl = __expf(wlogm[j]);
        float wt = __expf(wttm[j]);
        float we = __expf(wexp[j]);
        sc[j]   = make_float4(wl * L2E, blogm[j] * L2E, -wt * L2E, -bttm[j] * L2E);
        sc[5+j] = make_float4(we, we * wt, we * wl, we * wl * wl);
    }
    __syncthreads();

    int v = blockIdx.x * blockDim.x + threadIdx.x;
    if (v >= nvec) return;

    float4 t4 = ttm4[v];
    float4 l4 = logm4[v];
    float tt[NS] = {t4.x, t4.y, t4.z, t4.w};
    float ll[NS] = {l4.x, l4.y, l4.z, l4.w};

    float s[NS]   = {0.f,0.f,0.f,0.f};
    float st[NS]  = {0.f,0.f,0.f,0.f};
    float sl[NS]  = {0.f,0.f,0.f,0.f};
    float sll[NS] = {0.f,0.f,0.f,0.f};

    // ---- Part 1: smile term, sigmoid term, derivatives of s(t,l) ----
    #pragma unroll
    for (int j = 0; j < J; ++j) {
        float4 pa = sc[j];
        float4 pb = sc[5+j];
        #pragma unroll
        for (int n = 0; n < NS; ++n) {
            float a2 = fmaf(ll[n], pa.x, pa.y);       // a * log2(e)
            float a  = a2 * LN2;
            float E  = ex2f(a2);                      // e^a
            float E2 = E * E;
            float t1 = fmaf(-2.f, rcpf(fmaf(E2, E1F, 1.f)), 1.f);  // tanh(a+0.5)
            float t2 = fmaf(-2.f, rcpf(E + 1.f), 1.f);             // tanh(a/2)
            float u1 = fmaf(-t1, t1, 1.f);
            float u2 = fmaf(-t2, t2, 1.f);
            float hu2 = 0.5f * u2;
            float g   = fmaf(a, t1, 5e-4f) - t2;
            float gp  = fmaf(a, u1, t1) - hu2;
            float mm  = u1 * fmaf(-a, t1, 1.f);
            float gpp = fmaf(t2, hu2, mm + mm);
            float rq  = rsqf(g);
            float T   = g * rq;                       // sqrt(g)
            float hgp = 0.5f * gp;
            float Tp  = hgp * rq;
            float rr  = rq * rq;
            float Tpp = fmaf(-(hgp * hgp), rr, 0.5f * gpp) * rq;

            float eb  = ex2f(fmaf(tt[n], pa.z, pa.w));  // e^{-b}
            float sg  = rcpf(1.f + eb);                 // sigmoid(b)
            float sgp = sg * sg * eb;                   // sigmoid'

            s[n]   = fmaf(pb.x, T * sg,   s[n]);
            st[n]  = fmaf(pb.y, T * sgp,  st[n]);
            sl[n]  = fmaf(pb.z, sg * Tp,  sl[n]);
            sll[n] = fmaf(pb.w, sg * Tpp, sll[n]);
        }
    }

    // ---- Layers via table: nearest-node Taylor of F, F', F'' ----
    float4 r0, r1v, r2v, r3v;
    float* p0 = &r0.x; float* p1 = &r1v.x; float* p2 = &r2v.x; float* p3 = &r3v.x;
    #pragma unroll
    for (int n = 0; n < NS; ++n) {
        int i = __float2int_rn(s[n] * TABIH);
        i = min(i, TABN - 1);                       // s >= 0 always
        float d = fmaf((float)i, -TABH, s[n]);
        float4 c = __ldg(&d_tab[i]);
        float F2v = fmaf(c.w, d, c.z);
        float F1v = fmaf(fmaf(0.5f * c.w, d, c.z), d, c.y);
        float Fv  = fmaf(fmaf(fmaf(0.16666667f * c.w, d, 0.5f * c.z), d, c.y), d, c.x);

        p0[n] = Fv;
        p1[n] = F1v * st[n];
        p2[n] = F1v * sl[n];
        p3[n] = fmaf(F2v, sl[n] * sl[n], F1v * sll[n]);
    }
    o0[v] = r0;
    o1[v] = r1v;
    o2[v] = r2v;
    o3[v] = r3v;
}

extern "C" void kernel_launch(void* const* d_in, const int* in_sizes, int n_in,
                              void* d_out, int out_size)
{
    const float* ttm  = (const float*)d_in[0];
    const float* logm = (const float*)d_in[1];

    table_kernel<<<TABN/256, 256>>>((const float*)d_in[7],
                                    (const float*)d_in[8],  (const float*)d_in[9],
                                    (const float*)d_in[10], (const float*)d_in[11],
                                    (const float*)d_in[12], (const float*)d_in[13]);

    int B = in_sizes[0];
    int nvec = B >> 2;                 // B = 2^21, divisible by 4
    int blocks = (nvec + 255) / 256;
    float* out = (float*)d_out;
    smile_kernel<<<blocks, 256>>>((const float4*)ttm, (const float4*)logm,
                                  (float4*)out,
                                  (float4*)(out + (size_t)B),
                                  (float4*)(out + 2*(size_t)B),
                                  (float4*)(out + 3*(size_t)B),
                                  (const float*)d_in[2], (const float*)d_in[3],
                                  (const float*)d_in[4], (const float*)d_in[5],
                                  (const float*)d_in[6],
                                  nvec);
}

// round 5
// speedup vs baseline: 1.5843x; 1.0640x over previous
#include <cuda_runtime.h>

typedef unsigned long long u64;

#define J 5
#define L2E 1.4426950408889634f
#define LN2 0.6931471805599453f
#define E1F 2.7182818284590452f

#define TABN 2048
#define TABH 0.0078125f      // 1/128
#define TABIH 128.0f

// F(s) table: {F, F', F'', F'''} at s = i/128
__device__ float4 d_tab[TABN];

// ---- scalar approx helpers ----
__device__ __forceinline__ float ex2f(float x){ float r; asm("ex2.approx.f32 %0,%1;":"=f"(r):"f"(x)); return r; }
__device__ __forceinline__ float rcpf(float x){ float r; asm("rcp.approx.f32 %0,%1;":"=f"(r):"f"(x)); return r; }
__device__ __forceinline__ float rsqf(float x){ float r; asm("rsqrt.approx.f32 %0,%1;":"=f"(r):"f"(x)); return r; }

// ---- packed f32x2 helpers (sm_103a) ----
__device__ __forceinline__ u64 fma2_(u64 a,u64 b,u64 c){u64 d;asm("fma.rn.f32x2 %0,%1,%2,%3;":"=l"(d):"l"(a),"l"(b),"l"(c));return d;}
__device__ __forceinline__ u64 mul2_(u64 a,u64 b){u64 d;asm("mul.rn.f32x2 %0,%1,%2;":"=l"(d):"l"(a),"l"(b));return d;}
__device__ __forceinline__ u64 add2_(u64 a,u64 b){u64 d;asm("add.rn.f32x2 %0,%1,%2;":"=l"(d):"l"(a),"l"(b));return d;}
__device__ __forceinline__ u64 pk2(float lo,float hi){u64 d;asm("mov.b64 %0,{%1,%2};":"=l"(d):"f"(lo),"f"(hi));return d;}
__device__ __forceinline__ void up2(u64 v,float&lo,float&hi){asm("mov.b64 {%0,%1},%2;":"=f"(lo),"=f"(hi):"l"(v));}
__device__ __forceinline__ u64 bc2(float x){ return pk2(x,x); }
__device__ __forceinline__ u64 ex2p(u64 x){float l,h;up2(x,l,h);return pk2(ex2f(l),ex2f(h));}
__device__ __forceinline__ u64 rcpp(u64 x){float l,h;up2(x,l,h);return pk2(rcpf(l),rcpf(h));}
__device__ __forceinline__ u64 rsqp(u64 x){float l,h;up2(x,l,h);return pk2(rsqf(l),rsqf(h));}

// Build table of F(s) = Wo.softplus(W2.softplus(r1*s + c1) + b2) + bo and
// its first three derivatives wrt the scalar s. One node per thread.
__global__ void table_kernel(const float* __restrict__ bexp,
                             const float* __restrict__ W1, const float* __restrict__ b1,
                             const float* __restrict__ W2, const float* __restrict__ b2,
                             const float* __restrict__ Wo, const float* __restrict__ bo)
{
    int i = blockIdx.x * blockDim.x + threadIdx.x;
    if (i >= TABN) return;
    float s = (float)i * TABH;

    float h1[J], d1[J], dd1[J], ddd1[J];
    for (int j = 0; j < J; ++j) {
        float r = 0.f, c = b1[j];
        for (int k = 0; k < J; ++k) {
            float w = W1[j*J + k];
            r += w;
            c += w * bexp[k];
        }
        float z  = r * s + c;
        float e  = expf(-fabsf(z));
        float inv = 1.f / (1.f + e);
        float sg  = (z >= 0.f) ? inv : 1.f - inv;
        float sg1 = sg * (1.f - sg);
        float sg2 = sg1 * (1.f - 2.f * sg);
        h1[j]   = fmaxf(z, 0.f) + log1pf(e);
        d1[j]   = sg * r;
        dd1[j]  = sg1 * r * r;
        ddd1[j] = sg2 * r * r * r;
    }

    float F = bo[0], F1 = 0.f, F2 = 0.f, F3 = 0.f;
    for (int j = 0; j < J; ++j) {
        float z2 = b2[j], q = 0.f, m = 0.f, n3 = 0.f;
        for (int k = 0; k < J; ++k) {
            float w = W2[j*J + k];
            z2 += w * h1[k];
            q  += w * d1[k];
            m  += w * dd1[k];
            n3 += w * ddd1[k];
        }
        float e  = expf(-fabsf(z2));
        float inv = 1.f / (1.f + e);
        float sg  = (z2 >= 0.f) ? inv : 1.f - inv;
        float sp  = fmaxf(z2, 0.f) + log1pf(e);
        float sg1 = sg * (1.f - sg);
        float sg2 = sg1 * (1.f - 2.f * sg);
        float wo = Wo[j];
        F  += wo * sp;
        F1 += wo * sg * q;
        F2 += wo * (sg1 * q * q + sg * m);
        F3 += wo * (sg2 * q * q * q + 3.f * sg1 * q * m + sg * n3);
    }
    d_tab[i] = make_float4(F, F1, F2, F3);
}

__global__ __launch_bounds__(256)
void smile_kernel(const float4* __restrict__ ttm4,
                  const float4* __restrict__ logm4,
                  float4* __restrict__ o0, float4* __restrict__ o1,
                  float4* __restrict__ o2, float4* __restrict__ o3,
                  const float* __restrict__ wlogm, const float* __restrict__ blogm,
                  const float* __restrict__ wttm,  const float* __restrict__ bttm,
                  const float* __restrict__ wexp,
                  int nvec)
{
    // Per-block broadcast-packed constants:
    // scb[j] = {wl*L2E, bl*L2E, -wt*L2E, -bt*L2E, we, we*wt, we*wl, we*wl^2}
    __shared__ u64 scb[J][8];
    if (threadIdx.x < J) {
        int j = threadIdx.x;
        float wl = __expf(wlogm[j]);
        float wt = __expf(wttm[j]);
        float we = __expf(wexp[j]);
        scb[j][0] = bc2(wl * L2E);
        scb[j][1] = bc2(blogm[j] * L2E);
        scb[j][2] = bc2(-wt * L2E);
        scb[j][3] = bc2(-bttm[j] * L2E);
        scb[j][4] = bc2(we);
        scb[j][5] = bc2(we * wt);
        scb[j][6] = bc2(we * wl);
        scb[j][7] = bc2(we * wl * wl);
    }
    __syncthreads();

    int v = blockIdx.x * blockDim.x + threadIdx.x;
    if (v >= nvec) return;

    float4 t4 = ttm4[v];
    float4 l4 = logm4[v];
    u64 tt2[2] = { pk2(t4.x, t4.y), pk2(t4.z, t4.w) };
    u64 ll2[2] = { pk2(l4.x, l4.y), pk2(l4.z, l4.w) };

    const u64 one2   = bc2(1.f);
    const u64 cm1    = bc2(-1.f);
    const u64 two2   = bc2(2.f);
    const u64 m2c    = bc2(-2.f);
    const u64 half2  = bc2(0.5f);
    const u64 nhalf2 = bc2(-0.5f);
    const u64 c5e4   = bc2(5e-4f);
    const u64 e2     = bc2(E1F);
    const u64 ln2_2  = bc2(LN2);

    u64 s2[2]  = {0ull, 0ull};
    u64 st2[2] = {0ull, 0ull};
    u64 sl2[2] = {0ull, 0ull};
    u64 sll2[2]= {0ull, 0ull};

    // ---- Part 1: packed smile/sigmoid terms + derivatives of s(t,l) ----
    #pragma unroll
    for (int j = 0; j < J; ++j) {
        u64 paX = scb[j][0], paY = scb[j][1], paZ = scb[j][2], paW = scb[j][3];
        u64 pbX = scb[j][4], pbY = scb[j][5], pbZ = scb[j][6], pbW = scb[j][7];
        #pragma unroll
        for (int p = 0; p < 2; ++p) {
            u64 a2  = fma2_(ll2[p], paX, paY);        // a * log2(e)
            u64 av  = mul2_(a2, ln2_2);               // a
            u64 nav = mul2_(av, cm1);                 // -a
            u64 bm  = fma2_(tt2[p], paZ, paW);        // -b * log2(e)
            u64 E   = ex2p(a2);                       // e^a
            u64 eb  = ex2p(bm);                       // e^{-b}
            u64 E2  = mul2_(E, E);
            u64 q2  = fma2_(E2, e2, one2);            // e*E^2 + 1
            u64 q1  = add2_(E, one2);                 // E + 1
            u64 q3  = add2_(eb, one2);                // 1 + e^{-b}
            u64 q12 = mul2_(q1, q2);
            u64 P   = mul2_(q12, q3);
            u64 R   = rcpp(P);                        // one rcp for all three
            u64 sg  = mul2_(R, q12);                  // 1/q3 = sigmoid(b)
            u64 r2v = mul2_(R, mul2_(q1, q3));        // 1/q2
            u64 r1v = mul2_(R, mul2_(q2, q3));        // 1/q1
            u64 t1  = fma2_(m2c, r2v, one2);          // tanh(a+0.5)
            u64 nt2 = fma2_(two2, r1v, cm1);          // -tanh(a/2)
            u64 t2  = mul2_(nt2, cm1);
            u64 nt1 = mul2_(t1, cm1);
            u64 u1  = fma2_(t1, nt1, one2);           // 1 - t1^2
            u64 u2  = fma2_(nt2, t2, one2);           // 1 - t2^2
            u64 hu2  = mul2_(half2, u2);
            u64 nhu2 = mul2_(nhalf2, u2);
            u64 g   = add2_(fma2_(av, t1, c5e4), nt2);          // a*t1 - t2 + 5e-4
            u64 gp  = add2_(fma2_(av, u1, t1), nhu2);           // t1 + a*u1 - u2/2
            u64 w   = fma2_(nav, t1, one2);                     // 1 - a*t1
            u64 mm  = mul2_(u1, w);
            u64 gpp = fma2_(t2, hu2, add2_(mm, mm));            // 2*u1*(1-a*t1) + t2*u2/2
            u64 rq  = rsqp(g);
            u64 T   = mul2_(g, rq);                   // sqrt(g)
            u64 hgp = mul2_(half2, gp);
            u64 Tp  = mul2_(hgp, rq);
            u64 rr  = mul2_(rq, rq);
            u64 nrr = mul2_(rr, cm1);
            u64 hh  = mul2_(hgp, hgp);
            u64 uu  = fma2_(hh, nrr, mul2_(half2, gpp));
            u64 Tpp = mul2_(uu, rq);
            u64 sgp = mul2_(mul2_(sg, sg), eb);       // sigmoid'(b)

            s2[p]   = fma2_(pbX, mul2_(T, sg),   s2[p]);
            st2[p]  = fma2_(pbY, mul2_(T, sgp),  st2[p]);
            sl2[p]  = fma2_(pbZ, mul2_(sg, Tp),  sl2[p]);
            sll2[p] = fma2_(pbW, mul2_(sg, Tpp), sll2[p]);
        }
    }

    // ---- unpack accumulators ----
    float s[4], st[4], sl[4], sll[4];
    up2(s2[0],  s[0],  s[1]);  up2(s2[1],  s[2],  s[3]);
    up2(st2[0], st[0], st[1]); up2(st2[1], st[2], st[3]);
    up2(sl2[0], sl[0], sl[1]); up2(sl2[1], sl[2], sl[3]);
    up2(sll2[0],sll[0],sll[1]);up2(sll2[1],sll[2],sll[3]);

    // ---- Layers via table: nearest-node Taylor of F, F', F'' ----
    float4 r0, r1o, r2o, r3o;
    float* p0 = &r0.x; float* p1 = &r1o.x; float* p2 = &r2o.x; float* p3 = &r3o.x;
    #pragma unroll
    for (int n = 0; n < 4; ++n) {
        int i = __float2int_rn(s[n] * TABIH);
        i = min(i, TABN - 1);                        // s >= 0 always
        float d = fmaf((float)i, -TABH, s[n]);
        float4 c = __ldg(&d_tab[i]);
        float F2v = fmaf(c.w, d, c.z);
        float F1v = fmaf(fmaf(0.5f * c.w, d, c.z), d, c.y);
        float Fv  = fmaf(fmaf(fmaf(0.16666667f * c.w, d, 0.5f * c.z), d, c.y), d, c.x);
        p0[n] = Fv;
        p1[n] = F1v * st[n];
        p2[n] = F1v * sl[n];
        p3[n] = fmaf(F2v, sl[n] * sl[n], F1v * sll[n]);
    }
    o0[v] = r0;
    o1[v] = r1o;
    o2[v] = r2o;
    o3[v] = r3o;
}

extern "C" void kernel_launch(void* const* d_in, const int* in_sizes, int n_in,
                              void* d_out, int out_size)
{
    const float* ttm  = (const float*)d_in[0];
    const float* logm = (const float*)d_in[1];

    table_kernel<<<TABN/256, 256>>>((const float*)d_in[7],
                                    (const float*)d_in[8],  (const float*)d_in[9],
                                    (const float*)d_in[10], (const float*)d_in[11],
                                    (const float*)d_in[12], (const float*)d_in[13]);

    int B = in_sizes[0];
    int nvec = B >> 2;                 // B = 2^21, divisible by 4
    int blocks = (nvec + 255) / 256;
    float* out = (float*)d_out;
    smile_kernel<<<blocks, 256>>>((const float4*)ttm, (const float4*)logm,
                                  (float4*)out,
                                  (float4*)(out + (size_t)B),
                                  (float4*)(out + 2*(size_t)B),
                                  (float4*)(out + 3*(size_t)B),
                                  (const float*)d_in[2], (const float*)d_in[3],
                                  (const float*)d_in[4], (const float*)d_in[5],
                                  (const float*)d_in[6],
                                  nvec);
}

// round 6
// speedup vs baseline: 1.6964x; 1.0707x over previous
#include <cuda_runtime.h>

typedef unsigned long long u64;

#define J 5
#define L2E 1.4426950408889634f
#define LN2 0.6931471805599453f
#define E1F 2.7182818284590452f

#define TABN 2048
#define TABH 0.0078125f      // 1/128
#define TABIH 128.0f

// F(s) table: {F, F', F'', F'''} at s = i/128
__device__ float4 d_tab[TABN];

// ---- scalar approx helpers ----
__device__ __forceinline__ float ex2f(float x){ float r; asm("ex2.approx.f32 %0,%1;":"=f"(r):"f"(x)); return r; }
__device__ __forceinline__ float rcpf(float x){ float r; asm("rcp.approx.f32 %0,%1;":"=f"(r):"f"(x)); return r; }
__device__ __forceinline__ float rsqf(float x){ float r; asm("rsqrt.approx.f32 %0,%1;":"=f"(r):"f"(x)); return r; }

// ---- packed f32x2 helpers (sm_103a) ----
__device__ __forceinline__ u64 fma2_(u64 a,u64 b,u64 c){u64 d;asm("fma.rn.f32x2 %0,%1,%2,%3;":"=l"(d):"l"(a),"l"(b),"l"(c));return d;}
__device__ __forceinline__ u64 mul2_(u64 a,u64 b){u64 d;asm("mul.rn.f32x2 %0,%1,%2;":"=l"(d):"l"(a),"l"(b));return d;}
__device__ __forceinline__ u64 add2_(u64 a,u64 b){u64 d;asm("add.rn.f32x2 %0,%1,%2;":"=l"(d):"l"(a),"l"(b));return d;}
__device__ __forceinline__ u64 pk2(float lo,float hi){u64 d;asm("mov.b64 %0,{%1,%2};":"=l"(d):"f"(lo),"f"(hi));return d;}
__device__ __forceinline__ void up2(u64 v,float&lo,float&hi){asm("mov.b64 {%0,%1},%2;":"=f"(lo),"=f"(hi):"l"(v));}
__device__ __forceinline__ u64 bc2(float x){ return pk2(x,x); }
__device__ __forceinline__ u64 ex2p(u64 x){float l,h;up2(x,l,h);return pk2(ex2f(l),ex2f(h));}
__device__ __forceinline__ u64 rcpp(u64 x){float l,h;up2(x,l,h);return pk2(rcpf(l),rcpf(h));}
__device__ __forceinline__ u64 rsqp(u64 x){float l,h;up2(x,l,h);return pk2(rsqf(l),rsqf(h));}

// Build table of F(s) = Wo.softplus(W2.softplus(r1*s + c1) + b2) + bo and
// its first three derivatives wrt the scalar s. One node per thread.
// Fast intrinsics throughout: table values carry ~1e-7 rel error, far below
// the 1e-4 approximation budget.
__global__ void table_kernel(const float* __restrict__ bexp,
                             const float* __restrict__ W1, const float* __restrict__ b1,
                             const float* __restrict__ W2, const float* __restrict__ b2,
                             const float* __restrict__ Wo, const float* __restrict__ bo)
{
    int i = blockIdx.x * blockDim.x + threadIdx.x;
    if (i >= TABN) return;
    float s = (float)i * TABH;

    float h1[J], d1[J], dd1[J], ddd1[J];
    #pragma unroll
    for (int j = 0; j < J; ++j) {
        float r = 0.f, c = b1[j];
        #pragma unroll
        for (int k = 0; k < J; ++k) {
            float w = W1[j*J + k];
            r += w;
            c = fmaf(w, bexp[k], c);
        }
        float z   = fmaf(r, s, c);
        float e   = ex2f(-fabsf(z) * L2E);          // exp(-|z|)
        float inv = rcpf(1.f + e);
        float sg  = (z >= 0.f) ? inv : 1.f - inv;   // sigmoid(z)
        float sg1 = sg * (1.f - sg);
        float sg2 = sg1 * (1.f - 2.f * sg);
        h1[j]   = fmaxf(z, 0.f) + __logf(1.f + e);  // softplus(z)
        d1[j]   = sg * r;
        dd1[j]  = sg1 * r * r;
        ddd1[j] = sg2 * r * r * r;
    }

    float F = bo[0], F1 = 0.f, F2 = 0.f, F3 = 0.f;
    #pragma unroll
    for (int j = 0; j < J; ++j) {
        float z2 = b2[j], q = 0.f, m = 0.f, n3 = 0.f;
        #pragma unroll
        for (int k = 0; k < J; ++k) {
            float w = W2[j*J + k];
            z2 = fmaf(w, h1[k], z2);
            q  = fmaf(w, d1[k], q);
            m  = fmaf(w, dd1[k], m);
            n3 = fmaf(w, ddd1[k], n3);
        }
        float e   = ex2f(-fabsf(z2) * L2E);
        float inv = rcpf(1.f + e);
        float sg  = (z2 >= 0.f) ? inv : 1.f - inv;
        float sp  = fmaxf(z2, 0.f) + __logf(1.f + e);
        float sg1 = sg * (1.f - sg);
        float sg2 = sg1 * (1.f - 2.f * sg);
        float wo = Wo[j];
        F  = fmaf(wo, sp, F);
        F1 = fmaf(wo, sg * q, F1);
        F2 = fmaf(wo, fmaf(sg1, q * q, sg * m), F2);
        F3 = fmaf(wo, sg2 * q * q * q + 3.f * sg1 * q * m + sg * n3, F3);
    }
    d_tab[i] = make_float4(F, F1, F2, F3);
}

__global__ __launch_bounds__(128)
void smile_kernel(const float4* __restrict__ ttm4,
                  const float4* __restrict__ logm4,
                  float4* __restrict__ o0, float4* __restrict__ o1,
                  float4* __restrict__ o2, float4* __restrict__ o3,
                  const float* __restrict__ wlogm, const float* __restrict__ blogm,
                  const float* __restrict__ wttm,  const float* __restrict__ bttm,
                  const float* __restrict__ wexp,
                  int nvec)
{
    // Per-block broadcast-packed constants:
    // scb[j] = {wl*L2E, bl*L2E, -wt*L2E, -bt*L2E, we, we*wt, we*wl, we*wl^2}
    __shared__ u64 scb[J][8];
    if (threadIdx.x < J) {
        int j = threadIdx.x;
        float wl = __expf(wlogm[j]);
        float wt = __expf(wttm[j]);
        float we = __expf(wexp[j]);
        scb[j][0] = bc2(wl * L2E);
        scb[j][1] = bc2(blogm[j] * L2E);
        scb[j][2] = bc2(-wt * L2E);
        scb[j][3] = bc2(-bttm[j] * L2E);
        scb[j][4] = bc2(we);
        scb[j][5] = bc2(we * wt);
        scb[j][6] = bc2(we * wl);
        scb[j][7] = bc2(we * wl * wl);
    }
    __syncthreads();

    int v = blockIdx.x * blockDim.x + threadIdx.x;
    if (v >= nvec) return;

    float4 t4 = ttm4[v];
    float4 l4 = logm4[v];
    u64 tt2[2] = { pk2(t4.x, t4.y), pk2(t4.z, t4.w) };
    u64 ll2[2] = { pk2(l4.x, l4.y), pk2(l4.z, l4.w) };

    const u64 one2   = bc2(1.f);
    const u64 cm1    = bc2(-1.f);
    const u64 two2   = bc2(2.f);
    const u64 m2c    = bc2(-2.f);
    const u64 half2  = bc2(0.5f);
    const u64 nhalf2 = bc2(-0.5f);
    const u64 c5e4   = bc2(5e-4f);
    const u64 e2     = bc2(E1F);
    const u64 ln2_2  = bc2(LN2);

    u64 s2[2]  = {0ull, 0ull};
    u64 st2[2] = {0ull, 0ull};
    u64 sl2[2] = {0ull, 0ull};
    u64 sll2[2]= {0ull, 0ull};

    // ---- Part 1: packed smile/sigmoid terms + derivatives of s(t,l) ----
    #pragma unroll
    for (int j = 0; j < J; ++j) {
        u64 paX = scb[j][0], paY = scb[j][1], paZ = scb[j][2], paW = scb[j][3];
        u64 pbX = scb[j][4], pbY = scb[j][5], pbZ = scb[j][6], pbW = scb[j][7];
        #pragma unroll
        for (int p = 0; p < 2; ++p) {
            u64 a2  = fma2_(ll2[p], paX, paY);        // a * log2(e)
            u64 av  = mul2_(a2, ln2_2);               // a
            u64 bm  = fma2_(tt2[p], paZ, paW);        // -b * log2(e)
            u64 E   = ex2p(a2);                       // e^a
            u64 eb  = ex2p(bm);                       // e^{-b}
            u64 E2  = mul2_(E, E);
            u64 q2  = fma2_(E2, e2, one2);            // e*E^2 + 1
            u64 q1  = add2_(E, one2);                 // E + 1
            u64 q3  = add2_(eb, one2);                // 1 + e^{-b}
            u64 q12 = mul2_(q1, q2);
            u64 P   = mul2_(q12, q3);
            u64 R   = rcpp(P);                        // one rcp for all three
            u64 sg  = mul2_(R, q12);                  // 1/q3 = sigmoid(b)
            u64 Rq3 = mul2_(R, q3);
            u64 r2v = mul2_(Rq3, q1);                 // 1/q2
            u64 r1v = mul2_(Rq3, q2);                 // 1/q1
            u64 t1  = fma2_(m2c, r2v, one2);          // tanh(a+0.5)
            u64 nt2 = fma2_(two2, r1v, cm1);          // -tanh(a/2)
            u64 t2  = mul2_(nt2, cm1);
            u64 nt1 = mul2_(t1, cm1);
            u64 nav = mul2_(av, cm1);                 // -a
            u64 u1  = fma2_(t1, nt1, one2);           // 1 - t1^2
            u64 u2  = fma2_(nt2, t2, one2);           // 1 - t2^2
            u64 g   = add2_(fma2_(av, t1, c5e4), nt2);          // a*t1 - t2 + 5e-4
            u64 gp  = fma2_(u2, nhalf2, fma2_(av, u1, t1));     // t1 + a*u1 - u2/2
            u64 w   = fma2_(nav, t1, one2);                     // 1 - a*t1
            u64 mm  = mul2_(u1, w);
            u64 ht2 = mul2_(t2, half2);
            u64 gpp = fma2_(ht2, u2, add2_(mm, mm));            // 2*u1*(1-a*t1) + t2*u2/2
            u64 rq  = rsqp(g);
            u64 T   = mul2_(g, rq);                   // sqrt(g)
            u64 hgp = mul2_(half2, gp);
            u64 Tp  = mul2_(hgp, rq);
            u64 rr  = mul2_(rq, rq);
            u64 nhgp = mul2_(hgp, cm1);
            u64 uu  = fma2_(mul2_(nhgp, hgp), rr, mul2_(half2, gpp));
            u64 Tpp = mul2_(uu, rq);
            u64 sgp = mul2_(mul2_(sg, sg), eb);       // sigmoid'(b)

            s2[p]   = fma2_(pbX, mul2_(T, sg),   s2[p]);
            st2[p]  = fma2_(pbY, mul2_(T, sgp),  st2[p]);
            sl2[p]  = fma2_(pbZ, mul2_(sg, Tp),  sl2[p]);
            sll2[p] = fma2_(pbW, mul2_(sg, Tpp), sll2[p]);
        }
    }

    // ---- unpack accumulators ----
    float s[4], st[4], sl[4], sll[4];
    up2(s2[0],  s[0],  s[1]);  up2(s2[1],  s[2],  s[3]);
    up2(st2[0], st[0], st[1]); up2(st2[1], st[2], st[3]);
    up2(sl2[0], sl[0], sl[1]); up2(sl2[1], sl[2], sl[3]);
    up2(sll2[0],sll[0],sll[1]);up2(sll2[1],sll[2],sll[3]);

    // ---- Layers via table: nearest-node Taylor of F, F', F'' ----
    float4 r0, r1o, r2o, r3o;
    float* p0 = &r0.x; float* p1 = &r1o.x; float* p2 = &r2o.x; float* p3 = &r3o.x;
    #pragma unroll
    for (int n = 0; n < 4; ++n) {
        int i = __float2int_rn(s[n] * TABIH);
        i = min(i, TABN - 1);                        // s >= 0 always
        float d = fmaf((float)i, -TABH, s[n]);
        float4 c = __ldg(&d_tab[i]);
        float F2v = fmaf(c.w, d, c.z);
        float F1v = fmaf(fmaf(0.5f * c.w, d, c.z), d, c.y);
        float Fv  = fmaf(fmaf(fmaf(0.16666667f * c.w, d, 0.5f * c.z), d, c.y), d, c.x);
        p0[n] = Fv;
        p1[n] = F1v * st[n];
        p2[n] = F1v * sl[n];
        p3[n] = fmaf(F2v, sl[n] * sl[n], F1v * sll[n]);
    }
    o0[v] = r0;
    o1[v] = r1o;
    o2[v] = r2o;
    o3[v] = r3o;
}

extern "C" void kernel_launch(void* const* d_in, const int* in_sizes, int n_in,
                              void* d_out, int out_size)
{
    const float* ttm  = (const float*)d_in[0];
    const float* logm = (const float*)d_in[1];

    table_kernel<<<TABN/128, 128>>>((const float*)d_in[7],
                                    (const float*)d_in[8],  (const float*)d_in[9],
                                    (const float*)d_in[10], (const float*)d_in[11],
                                    (const float*)d_in[12], (const float*)d_in[13]);

    int B = in_sizes[0];
    int nvec = B >> 2;                 // B = 2^21, divisible by 4
    int blocks = (nvec + 127) / 128;
    float* out = (float*)d_out;
    smile_kernel<<<blocks, 128>>>((const float4*)ttm, (const float4*)logm,
                                  (float4*)out,
                                  (float4*)(out + (size_t)B),
                                  (float4*)(out + 2*(size_t)B),
                                  (float4*)(out + 3*(size_t)B),
                                  (const float*)d_in[2], (const float*)d_in[3],
                                  (const float*)d_in[4], (const float*)d_in[5],
                                  (const float*)d_in[6],
                                  nvec);
}